// round 9
// baseline (speedup 1.0000x reference)
#include <cuda_runtime.h>
#include <cuda_fp16.h>
#include <cstdint>

// BMM_S8T_S8N_F16T producer/consumer persistent kernel:
//  148 CTAs (1/SM), 384 threads: warps 0-7 compute (16-row slab each:
//  IMMA cols 0..71 + dp4a cols 72..127), warps 8-11 load+pack the NEXT tile
//  into the other smem buffer. Named-barrier FULL/FREE handshake per buffer.
// out[b,m,n] = f32( fp16_round( alpha * sum_k a[b,m,k]*b[b,n,k] ) )

#define MDIM 1024
#define NDIM 1024
#define KDIM 128
#define NTILES 4096
#define NCTAS 148

#define ROWSTRIDE 36
#define NI_MMA 9
#define COL_DP 72
#define NI_DP 7

#define BAR_FULL0 1
#define BAR_FULL1 2
#define BAR_FREE0 3
#define BAR_FREE1 4
#define BAR_CNT   384

#define PACK4(v) __byte_perm(__byte_perm((v).x, (v).y, 0x0040), \
                             __byte_perm((v).z, (v).w, 0x0040), 0x5410)

#define BAR_SYNC(id)   asm volatile("bar.sync %0, %1;"   :: "r"(id), "r"(BAR_CNT) : "memory")
#define BAR_ARRIVE(id) asm volatile("bar.arrive %0, %1;" :: "r"(id), "r"(BAR_CNT) : "memory")

__global__ __launch_bounds__(384, 1)
void bmm_s8_prodcons_kernel(const int* __restrict__ A,
                            const int* __restrict__ Bmat,
                            const float* __restrict__ alpha_p,
                            float* __restrict__ Out) {
    __shared__ uint32_t As[2][128 * ROWSTRIDE];
    __shared__ uint32_t Bs[2][128 * ROWSTRIDE];

    const int tid  = threadIdx.x;
    const int lane = tid & 31;
    const int wid  = tid >> 5;

    if (wid >= 8) {
        // ================== LOADER WARPS (128 threads) ==================
        const int ltid = tid - 256;          // 0..127
        int i = 0;
        for (int t = blockIdx.x; t < NTILES; t += NCTAS, i++) {
            const int b = i & 1;
            if (i >= 2) BAR_SYNC(BAR_FREE0 + b);

            const int bn = t & 7, bm = (t >> 3) & 7, bz = t >> 6;
            const int* Ab = A    + ((size_t)bz * MDIM + bm * 128) * KDIM;
            const int* Bb = Bmat + ((size_t)bz * NDIM + bn * 128) * KDIM;

            // 4096 packed words per operand; 128 lanes x 32 words each.
            // Process in 4 batches of 8 (A and B per batch) for MLP.
            #pragma unroll
            for (int bt = 0; bt < 4; bt++) {
                int4 va[8], vb[8];
                #pragma unroll
                for (int u = 0; u < 8; u++) {
                    int idx = ltid + (bt * 8 + u) * 128;   // 0..4095
                    int row = idx >> 5, q = idx & 31;      // q = word in row
                    va[u] = *(const int4*)(Ab + row * KDIM + q * 4);
                    vb[u] = *(const int4*)(Bb + row * KDIM + q * 4);
                }
                #pragma unroll
                for (int u = 0; u < 8; u++) {
                    int idx = ltid + (bt * 8 + u) * 128;
                    int row = idx >> 5, q = idx & 31;
                    As[b][row * ROWSTRIDE + q] = PACK4(va[u]);
                    Bs[b][row * ROWSTRIDE + q] = PACK4(vb[u]);
                }
            }
            BAR_ARRIVE(BAR_FULL0 + b);
        }
        return;
    }

    // ================== COMPUTE WARPS (256 threads) ==================
    const int rb = wid * 16;
    const int lq = lane >> 2;
    const int lr = lane & 3;
    const int g  = lane >> 3;
    const int j  = lane & 7;
    const float alpha = *alpha_p;

    int i = 0;
    for (int t = blockIdx.x; t < NTILES; t += NCTAS, i++) {
        const int b = i & 1;
        BAR_SYNC(BAR_FULL0 + b);

        int macc[NI_MMA][4];
        #pragma unroll
        for (int ni = 0; ni < NI_MMA; ni++)
            #pragma unroll
            for (int r = 0; r < 4; r++) macc[ni][r] = 0;

        int dacc[4][NI_DP];
        #pragma unroll
        for (int mi = 0; mi < 4; mi++)
            #pragma unroll
            for (int ni = 0; ni < NI_DP; ni++) dacc[mi][ni] = 0;

        #pragma unroll
        for (int ks = 0; ks < 4; ks++) {
            // --- IMMA: cols 0..71 ---
            uint32_t af[4];
            {
                const uint32_t* p = &As[b][(rb + lq) * ROWSTRIDE + ks * 8 + lr];
                af[0] = p[0];  af[2] = p[4];
                const uint32_t* p8 = p + 8 * ROWSTRIDE;
                af[1] = p8[0]; af[3] = p8[4];
            }
            #pragma unroll
            for (int ni = 0; ni < NI_MMA; ni++) {
                const uint32_t* q = &Bs[b][(ni * 8 + lq) * ROWSTRIDE + ks * 8 + lr];
                uint32_t b0 = q[0], b1 = q[4];
                asm volatile(
                    "mma.sync.aligned.m16n8k32.row.col.s32.s8.s8.s32 "
                    "{%0,%1,%2,%3}, {%4,%5,%6,%7}, {%8,%9}, {%0,%1,%2,%3};"
                    : "+r"(macc[ni][0]), "+r"(macc[ni][1]),
                      "+r"(macc[ni][2]), "+r"(macc[ni][3])
                    : "r"(af[0]), "r"(af[1]), "r"(af[2]), "r"(af[3]),
                      "r"(b0), "r"(b1));
            }
            // --- dp4a: cols 72..127 ---
            #pragma unroll
            for (int c = 0; c < 2; c++) {
                const int kw = ks * 8 + c * 4;
                uint4 av[4];
                #pragma unroll
                for (int mi = 0; mi < 4; mi++)
                    av[mi] = *(const uint4*)&As[b][(rb + g + 4 * mi) * ROWSTRIDE + kw];
                #pragma unroll
                for (int ni = 0; ni < NI_DP; ni++) {
                    uint4 bv = *(const uint4*)&Bs[b][(COL_DP + j + 8 * ni) * ROWSTRIDE + kw];
                    #pragma unroll
                    for (int mi = 0; mi < 4; mi++) {
                        int v = dacc[mi][ni];
                        v = __dp4a((int)av[mi].x, (int)bv.x, v);
                        v = __dp4a((int)av[mi].y, (int)bv.y, v);
                        v = __dp4a((int)av[mi].z, (int)bv.z, v);
                        v = __dp4a((int)av[mi].w, (int)bv.w, v);
                        dacc[mi][ni] = v;
                    }
                }
            }
        }

        BAR_ARRIVE(BAR_FREE0 + b);   // smem reads done; loaders may refill

        // --- Epilogue (registers only) ---
        const int bn = t & 7, bm = (t >> 3) & 7, bz = t >> 6;
        float* obase = Out + ((size_t)bz * MDIM + bm * 128) * NDIM + bn * 128;

        #pragma unroll
        for (int ni = 0; ni < NI_MMA; ni++) {
            int c0 = ni * 8 + lr * 2;
            float2 v0;
            v0.x = __half2float(__float2half_rn(alpha * (float)macc[ni][0]));
            v0.y = __half2float(__float2half_rn(alpha * (float)macc[ni][1]));
            *(float2*)(obase + (size_t)(rb + lq) * NDIM + c0) = v0;
            float2 v1;
            v1.x = __half2float(__float2half_rn(alpha * (float)macc[ni][2]));
            v1.y = __half2float(__float2half_rn(alpha * (float)macc[ni][3]));
            *(float2*)(obase + (size_t)(rb + lq + 8) * NDIM + c0) = v1;
        }
        #pragma unroll
        for (int mi = 0; mi < 4; mi++) {
            float* orow = obase + (size_t)(rb + g + 4 * mi) * NDIM;
            #pragma unroll
            for (int ni = 0; ni < NI_DP; ni++) {
                int col = COL_DP + j + 8 * ni;
                orow[col] = __half2float(__float2half_rn(alpha * (float)dacc[mi][ni]));
            }
        }
    }
}

extern "C" void kernel_launch(void* const* d_in, const int* in_sizes, int n_in,
                              void* d_out, int out_size) {
    // alpha is the size-1 input; the two large tensors are a then b in index order.
    int ai = -1, bi = -1, si = -1;
    for (int i = 0; i < n_in; i++) {
        if (in_sizes[i] == 1) { si = i; }
        else if (ai < 0)      { ai = i; }
        else                  { bi = i; }
    }
    const int*   a     = (const int*)d_in[ai];
    const int*   b     = (const int*)d_in[bi];
    const float* alpha = (const float*)d_in[si];
    float*       out   = (float*)d_out;

    bmm_s8_prodcons_kernel<<<NCTAS, 384>>>(a, b, alpha, out);
}